// round 5
// baseline (speedup 1.0000x reference)
#include <cuda_runtime.h>
#include <cuda.h>
#include <cstdint>

// LZC48 over binary float spikes: [n_words, 48] f32 {0,1} -> [n_words, 6] f32.
//
// R5: byte floor is fixed at ~306 MB (128B line-granular DRAM fetch, one line
// per word, 2 of 3 lines touched). This round attacks duty cycle: each block
// processes 8 tiles with double-buffered TMA loads so a DRAM request stream is
// in flight continuously; single logical wave (512 blocks, ~5/SM).

constexpr int TPB  = 256;
constexpr int WPB  = 512;                  // words per tile
constexpr int TILES_PER_BLOCK = 8;
constexpr unsigned TILE_BYTES = WPB * 32;  // 16384

__device__ __forceinline__ void mbar_wait(unsigned mb, unsigned parity)
{
    unsigned done;
    asm volatile(
        "{\n\t.reg .pred p;\n\t"
        "mbarrier.try_wait.parity.shared::cta.b64 p, [%1], %2;\n\t"
        "selp.b32 %0, 1, 0, p;\n\t}"
        : "=r"(done) : "r"(mb), "r"(parity) : "memory");
    while (!done) {
        asm volatile(
            "{\n\t.reg .pred p;\n\t"
            "mbarrier.try_wait.parity.shared::cta.b64 p, [%1], %2, 0x989680;\n\t"
            "selp.b32 %0, 1, 0, p;\n\t}"
            : "=r"(done) : "r"(mb), "r"(parity) : "memory");
    }
}

__global__ __launch_bounds__(TPB)
void lzc48_pipe_kernel(const __grid_constant__ CUtensorMap tmap,
                       const uint4* __restrict__ in4,   // raw input, fallback scan
                       float* __restrict__ out,
                       int n_words)
{
    __shared__ __align__(128) uint4 buf[2][WPB * 2];     // 2 x 16 KB
    __shared__ float sout[WPB * 6];                      // 12 KB
    __shared__ __align__(8) unsigned long long mbar[2];

    const int t = threadIdx.x;
    const int base_tile = blockIdx.x * TILES_PER_BLOCK;
    const unsigned mb0 = (unsigned)__cvta_generic_to_shared(&mbar[0]);
    const unsigned mb1 = (unsigned)__cvta_generic_to_shared(&mbar[1]);
    const CUtensorMap* tp = &tmap;

    if (t == 0) {
        asm volatile("mbarrier.init.shared::cta.b64 [%0], 1;" :: "r"(mb0) : "memory");
        asm volatile("mbarrier.init.shared::cta.b64 [%0], 1;" :: "r"(mb1) : "memory");
    }
    __syncthreads();

    auto issue = [&](int i) {   // t == 0 only
        const unsigned mb = (i & 1) ? mb1 : mb0;
        const int w0 = (base_tile + i) * WPB;
        unsigned s0 = (unsigned)__cvta_generic_to_shared(&buf[i & 1][0]);
        unsigned s1 = (unsigned)__cvta_generic_to_shared(&buf[i & 1][512]);
        asm volatile("mbarrier.arrive.expect_tx.shared::cta.b64 _, [%0], %1;"
                     :: "r"(mb), "r"(TILE_BYTES) : "memory");
        asm volatile("cp.async.bulk.tensor.2d.shared::cta.global.tile.mbarrier::complete_tx::bytes "
                     "[%0], [%1, {%2, %3}], [%4];"
                     :: "r"(s0), "l"(tp), "r"(0), "r"(w0), "r"(mb) : "memory");
        asm volatile("cp.async.bulk.tensor.2d.shared::cta.global.tile.mbarrier::complete_tx::bytes "
                     "[%0], [%1, {%2, %3}], [%4];"
                     :: "r"(s1), "l"(tp), "r"(0), "r"(w0 + 256), "r"(mb) : "memory");
    };

    if (t == 0 && base_tile * WPB < n_words) issue(0);

    for (int i = 0; i < TILES_PER_BLOCK; i++) {
        const int tile0 = (base_tile + i) * WPB;
        if (tile0 >= n_words) break;
        int count = n_words - tile0;
        if (count > WPB) count = WPB;

        // Prefetch next tile into the other buffer (consumed two iters ago).
        if (t == 0 && i + 1 < TILES_PER_BLOCK && (base_tile + i + 1) * WPB < n_words)
            issue(i + 1);

        mbar_wait((i & 1) ? mb1 : mb0, (unsigned)((i >> 1) & 1));
        const uint4* __restrict__ tb = buf[i & 1];

        // ---- decode 2 words per thread ----
        #pragma unroll
        for (int k = 0; k < 2; k++) {
            const int wl = t + k * TPB;
            if (wl >= count) break;
            uint4 e = tb[wl * 2];
            uint4 o = tb[wl * 2 + 1];
            unsigned m = (e.x ? 128u : 0u) | (e.y ? 64u : 0u) | (e.z ? 32u : 0u) | (e.w ? 16u : 0u)
                       | (o.x ?   8u : 0u) | (o.y ?  4u : 0u) | (o.z ?  2u : 0u) | (o.w ?  1u : 0u);
            int lzc;
            if (m) {
                lzc = __clz(m << 24);
            } else {                                  // P = 1/256 fallback
                const uint4* wp = in4 + (size_t)(tile0 + wl) * 12;
                unsigned long long acc = 0ull;
                #pragma unroll
                for (int j = 2; j < 12; j++) {
                    uint4 v = __ldcg(wp + j);
                    unsigned nib = (v.x ? 8u : 0u) | (v.y ? 4u : 0u)
                                 | (v.z ? 2u : 0u) | (v.w ? 1u : 0u);
                    acc = (acc << 4) | nib;
                }
                lzc = acc ? (8 + __clzll(acc << 24)) : 48;
            }
            float* so = sout + wl * 6;
            so[0] = (float)((lzc >> 5) & 1);
            so[1] = (float)((lzc >> 4) & 1);
            so[2] = (float)((lzc >> 3) & 1);
            so[3] = (float)((lzc >> 2) & 1);
            so[4] = (float)((lzc >> 1) & 1);
            so[5] = (float)( lzc       & 1);
        }
        __syncthreads();   // sout complete; buf[i&1] fully consumed

        // ---- coalesced store: 512*6 floats = 768 float4 ----
        if (count == WPB) {
            float4* ob = reinterpret_cast<float4*>(out + (size_t)tile0 * 6);
            const float4* sb = reinterpret_cast<const float4*>(sout);
            #pragma unroll
            for (int k = 0; k < 3; k++)
                ob[k * TPB + t] = sb[k * TPB + t];
        } else {
            for (int j = t; j < count * 6; j += TPB)
                out[(size_t)tile0 * 6 + j] = sout[j];
        }
        __syncthreads();   // sout reusable next iteration
    }
}

// ------------------------------------------------------------ fallback (R1)
__global__ __launch_bounds__(TPB)
void lzc48_ldg_kernel(const uint4* __restrict__ in4, float* __restrict__ out,
                      int n_words)
{
    __shared__ uint4 sbuf[520];
    __shared__ float sout[256 * 6];

    const int tile = blockIdx.x * 256;
    int count = n_words - tile;
    if (count > 256) count = 256;

    #pragma unroll
    for (int k = 0; k < 2; k++) {
        int j = k * TPB + threadIdx.x;
        int w = j >> 1, h = j & 1;
        if (w < count)
            sbuf[(h ? 260 : 0) + w] = in4[(size_t)(tile + w) * 12 + h];
    }
    __syncthreads();

    const int t = threadIdx.x;
    if (t < count) {
        uint4 e = sbuf[t], o = sbuf[260 + t];
        unsigned m = (e.x ? 128u : 0u) | (e.y ? 64u : 0u) | (e.z ? 32u : 0u) | (e.w ? 16u : 0u)
                   | (o.x ?   8u : 0u) | (o.y ?  4u : 0u) | (o.z ?  2u : 0u) | (o.w ?  1u : 0u);
        int lzc;
        if (m) lzc = __clz(m << 24);
        else {
            const uint4* wp = in4 + (size_t)(tile + t) * 12;
            unsigned long long acc = 0ull;
            #pragma unroll
            for (int i = 2; i < 12; i++) {
                uint4 v = wp[i];
                unsigned nib = (v.x ? 8u : 0u) | (v.y ? 4u : 0u)
                             | (v.z ? 2u : 0u) | (v.w ? 1u : 0u);
                acc = (acc << 4) | nib;
            }
            lzc = acc ? (8 + __clzll(acc << 24)) : 48;
        }
        float* so = sout + t * 6;
        so[0] = (float)((lzc >> 5) & 1); so[1] = (float)((lzc >> 4) & 1);
        so[2] = (float)((lzc >> 3) & 1); so[3] = (float)((lzc >> 2) & 1);
        so[4] = (float)((lzc >> 1) & 1); so[5] = (float)( lzc       & 1);
    }
    __syncthreads();

    if (count == 256) {
        float4* ob = reinterpret_cast<float4*>(out + (size_t)tile * 6);
        const float4* sb = reinterpret_cast<const float4*>(sout);
        ob[t] = sb[t];
        if (t < 128) ob[TPB + t] = sb[TPB + t];
    } else {
        for (int j = t; j < count * 6; j += TPB)
            out[(size_t)tile * 6 + j] = sout[j];
    }
}

// ----------------------------------------------------------------- launcher
typedef CUresult (*EncodeTiledFn)(
    CUtensorMap*, CUtensorMapDataType, cuuint32_t, void*,
    const cuuint64_t*, const cuuint64_t*, const cuuint32_t*, const cuuint32_t*,
    CUtensorMapInterleave, CUtensorMapSwizzle, CUtensorMapL2promotion,
    CUtensorMapFloatOOBfill);

static EncodeTiledFn get_encode_fn()
{
    void* fn = nullptr;
    cudaDriverEntryPointQueryResult qres = cudaDriverEntryPointSymbolNotFound;
    if (cudaGetDriverEntryPointByVersion("cuTensorMapEncodeTiled", &fn, 12000,
                                         cudaEnableDefault, &qres) == cudaSuccess
        && qres == cudaDriverEntryPointSuccess && fn)
        return (EncodeTiledFn)fn;
    fn = nullptr;
    qres = cudaDriverEntryPointSymbolNotFound;
    if (cudaGetDriverEntryPoint("cuTensorMapEncodeTiled", &fn,
                                cudaEnableDefault, &qres) == cudaSuccess
        && qres == cudaDriverEntryPointSuccess && fn)
        return (EncodeTiledFn)fn;
    return nullptr;
}

extern "C" void kernel_launch(void* const* d_in, const int* in_sizes, int n_in,
                              void* d_out, int out_size)
{
    const uint4* in4 = (const uint4*)d_in[0];
    float* out = (float*)d_out;
    const int n_words = in_sizes[0] / 48;   // 2,097,152

    bool tma_ok = false;
    CUtensorMap tmap;
    EncodeTiledFn encode = get_encode_fn();
    if (encode) {
        cuuint64_t dims[2]    = { 48, (cuuint64_t)n_words };
        cuuint64_t strides[1] = { 192 };
        cuuint32_t box[2]     = { 8, 256 };
        cuuint32_t estr[2]    = { 1, 1 };
        CUresult r = encode(&tmap, CU_TENSOR_MAP_DATA_TYPE_FLOAT32, 2,
                            (void*)in4, dims, strides, box, estr,
                            CU_TENSOR_MAP_INTERLEAVE_NONE,
                            CU_TENSOR_MAP_SWIZZLE_NONE,
                            CU_TENSOR_MAP_L2_PROMOTION_NONE,
                            CU_TENSOR_MAP_FLOAT_OOB_FILL_NONE);
        tma_ok = (r == CUDA_SUCCESS);
    }

    if (tma_ok) {
        const int words_per_block = WPB * TILES_PER_BLOCK;               // 4096
        const int grid = (n_words + words_per_block - 1) / words_per_block; // 512
        lzc48_pipe_kernel<<<grid, TPB>>>(tmap, in4, out, n_words);
    } else {
        const int grid = (n_words + 255) / 256;
        lzc48_ldg_kernel<<<grid, TPB>>>(in4, out, n_words);
    }
}

// round 7
// speedup vs baseline: 1.0769x; 1.0769x over previous
#include <cuda_runtime.h>
#include <cstdint>

// LZC48 over binary float spikes: [n_words, 48] f32 {0,1} -> [n_words, 6] f32.
//
// R7 (= R6 retest after infra failure): byte floor is 306 MB (128B
// line-granular DRAM fetch; 192B word stride puts every word's prefix in its
// own line, touching 2 of 3 lines). Best structure is R1's paired-lane load
// (1 L1 wavefront per word). This round keeps that geometry but removes the
// input smem round-trip + barrier: adjacent lanes load the two 16B halves of
// a word and combine via shfl_xor. 4 independent LDG.128 per thread
// (512 words/block), conflict-free split encode (even lane writes bits 5..3,
// odd lane bits 2..0).

constexpr int TPB = 256;
constexpr int WPB = 512;    // words per block

__global__ __launch_bounds__(TPB)
void lzc48_kernel(const uint4* __restrict__ in4,   // word w at in4[w*12 .. w*12+11]
                  float* __restrict__ out,         // [n_words*6]
                  int n_words)
{
    __shared__ float sout[WPB * 6];                // 12 KB output staging

    const int t    = threadIdx.x;
    const int tile = blockIdx.x * WPB;
    int count = n_words - tile;
    if (count > WPB) count = WPB;

    const int h = t & 1;                           // half index (0 = floats 0..3)

    // ---- issue all 4 independent sector-half loads up front ----
    // j = r*TPB + t; word w = j>>1; lanes 2i/2i+1 load the two halves of one
    // word's 32B prefix -> both in the same 128B line, 1 wavefront per word.
    uint4 v[4];
    int   w[4];
    bool  act[4];
    #pragma unroll
    for (int r = 0; r < 4; r++) {
        int j = r * TPB + t;                       // 0..1023
        w[r]   = j >> 1;                           // 0..511
        act[r] = (w[r] < count);
        if (act[r]) v[r] = __ldcg(in4 + (size_t)(tile + w[r]) * 12 + h);
        else        v[r] = make_uint4(0u, 0u, 0u, 0u);
    }

    // ---- decode: combine halves via shfl, encode 3 bits per lane ----
    #pragma unroll
    for (int r = 0; r < 4; r++) {
        // 4-bit nibble of this half, MSB-first within the half.
        unsigned nib = (v[r].x ? 8u : 0u) | (v[r].y ? 4u : 0u)
                     | (v[r].z ? 2u : 0u) | (v[r].w ? 1u : 0u);
        // Even lane holds bits 7..4, odd lane bits 3..0 of the 8-bit mask.
        unsigned m = h ? nib : (nib << 4);
        m |= __shfl_xor_sync(0xFFFFFFFFu, m, 1);   // both lanes: full 8-bit mask

        if (act[r]) {
            int lzc;
            if (m) {
                lzc = __clz(m << 24);              // 0..7
            } else {                               // P = 1/256: scan floats 8..47
                const uint4* wp = in4 + (size_t)(tile + w[r]) * 12;
                unsigned long long acc = 0ull;
                #pragma unroll
                for (int i = 2; i < 12; i++) {
                    uint4 q = __ldcg(wp + i);
                    unsigned n2 = (q.x ? 8u : 0u) | (q.y ? 4u : 0u)
                                | (q.z ? 2u : 0u) | (q.w ? 1u : 0u);
                    acc = (acc << 4) | n2;         // 40 bits; bit39 = float 8
                }
                lzc = acc ? (8 + __clzll(acc << 24)) : 48;
            }
            // Split encode: even lane writes bits 5,4,3; odd lane bits 2,1,0.
            // STS addresses stride 3 floats per lane -> conflict-free.
            float* so = sout + w[r] * 6 + 3 * h;
            const int s = 5 - 3 * h;
            so[0] = (float)((lzc >> (s    )) & 1);
            so[1] = (float)((lzc >> (s - 1)) & 1);
            so[2] = (float)((lzc >> (s - 2)) & 1);
        }
    }
    __syncthreads();

    // ---- coalesced store: 512*6 floats = 768 float4 per block ----
    if (count == WPB) {
        float4* ob = reinterpret_cast<float4*>(out + (size_t)tile * 6);
        const float4* sb = reinterpret_cast<const float4*>(sout);
        #pragma unroll
        for (int k = 0; k < 3; k++)
            ob[k * TPB + t] = sb[k * TPB + t];
    } else {
        for (int j = t; j < count * 6; j += TPB)
            out[(size_t)tile * 6 + j] = sout[j];
    }
}

extern "C" void kernel_launch(void* const* d_in, const int* in_sizes, int n_in,
                              void* d_out, int out_size)
{
    const uint4* in4 = (const uint4*)d_in[0];
    float* out = (float*)d_out;
    const int n_words = in_sizes[0] / 48;          // 2,097,152
    const int grid = (n_words + WPB - 1) / WPB;    // 4096
    lzc48_kernel<<<grid, TPB>>>(in4, out, n_words);
}

// round 8
// speedup vs baseline: 1.1200x; 1.0400x over previous
#include <cuda_runtime.h>
#include <cstdint>

// LZC48 over binary float spikes.
// Input:  [n_words, 48] float32, values exactly 0.0f or 1.0f, MSB first.
// Output: [n_words, 6]  float32, 6-bit MSB-first encoding of leading-zero count
//         (48 -> 110000 for an all-zero word).
//
// R8: converged champion (= R1). Measured facts driving this design:
//   * DRAM fetch is 128B line-granular on this part (LDG and TMA identical;
//     L2_PROMOTION_NONE has no effect). With 192B word stride, each word's
//     32B prefix occupies its own line; lines {3k,3k+1} touched, {3k+2} not.
//     -> byte floor 256MB read + 50MB write = 306MB, achieved ~6.3TB/s
//     -> ~48us is the wall. Five structural variants all land 74-79% DRAM.
//   * Paired-lane loads (lanes 2i,2i+1 take the two 16B halves of word i's
//     prefix) give 1 L1 wavefront per word.
//   * Fallback (prefix all zero, P=1/256) scans floats 8..47; for even words
//     those bytes are in already-fetched lines (L2 hits), so it adds ~nothing.

constexpr int TPB = 256;   // threads per block
constexpr int WPB = 256;   // words per block

__global__ __launch_bounds__(TPB)
void lzc48_kernel(const uint4* __restrict__ in4,   // word w at in4[w*12 .. w*12+11]
                  float* __restrict__ out,         // [n_words*6]
                  int n_words)
{
    // even halves at sbuf[0..255], odd halves at sbuf[260..515].
    // The 260 offset (byte 4160, == 64 mod 128) makes the interleaved
    // even/odd STS.128 pattern conflict-free in every 8-lane phase.
    __shared__ uint4 sbuf[520];
    __shared__ float sout[WPB * 6];

    const int tile  = blockIdx.x * WPB;
    int count = n_words - tile;
    if (count > WPB) count = WPB;

    // ---- Load sector 0 (first 8 floats = 32B) of each word in the tile ----
    // j = 2*word + half. Lanes (2i, 2i+1) load the two 16B halves of word i's
    // prefix; both fall in the same 128B line -> 1 wavefront per word.
    #pragma unroll
    for (int k = 0; k < 2; k++) {
        int j = k * TPB + threadIdx.x;          // 0 .. 511
        int w = j >> 1;
        int h = j & 1;
        if (w < count) {
            uint4 v = in4[(size_t)(tile + w) * 12 + h];
            sbuf[(h ? 260 : 0) + w] = v;
        }
    }
    __syncthreads();

    const int t = threadIdx.x;
    if (t < count) {
        uint4 e = sbuf[t];         // floats 0..3 of the word (MSB side)
        uint4 o = sbuf[260 + t];   // floats 4..7

        // 8-bit mask, bit7 = float0 (MSB first). Inputs are exactly 0.0f/1.0f,
        // so a nonzero bit pattern <=> value 1.0f.
        unsigned m = (e.x ? 128u : 0u) | (e.y ? 64u : 0u) | (e.z ? 32u : 0u) | (e.w ? 16u : 0u)
                   | (o.x ?   8u : 0u) | (o.y ?  4u : 0u) | (o.z ?  2u : 0u) | (o.w ?  1u : 0u);

        int lzc;
        if (m) {
            lzc = __clz(m << 24);              // 0..7
        } else {
            // Rare fallback (P = 1/256): scan remaining 40 floats.
            const uint4* wp = in4 + (size_t)(tile + t) * 12;
            unsigned long long acc = 0ull;
            #pragma unroll
            for (int i = 2; i < 12; i++) {
                uint4 v = wp[i];
                unsigned nib = (v.x ? 8u : 0u) | (v.y ? 4u : 0u)
                             | (v.z ? 2u : 0u) | (v.w ? 1u : 0u);
                acc = (acc << 4) | nib;        // 40 bits; bit39 = float 8
            }
            lzc = acc ? (8 + __clzll(acc << 24)) : 48;
        }

        // 6-bit MSB-first encoding into smem staging (stride 6 floats:
        // STS.64x3 is conflict-free: 6t mod 32 distinct over each 16-lane phase).
        float* so = sout + t * 6;
        so[0] = (float)((lzc >> 5) & 1);
        so[1] = (float)((lzc >> 4) & 1);
        so[2] = (float)((lzc >> 3) & 1);
        so[3] = (float)((lzc >> 2) & 1);
        so[4] = (float)((lzc >> 1) & 1);
        so[5] = (float)( lzc       & 1);
    }
    __syncthreads();

    // ---- Coalesced write of the tile's 256*6 floats = 384 float4 ----
    if (count == WPB) {
        float4* ob = reinterpret_cast<float4*>(out + (size_t)tile * 6);
        const float4* sb = reinterpret_cast<const float4*>(sout);
        ob[t] = sb[t];
        if (t < (WPB * 6 / 4) - TPB)           // remaining 128 float4
            ob[TPB + t] = sb[TPB + t];
    } else {
        // Partial last tile: scalar writes, no overrun into the next tile.
        for (int j = t; j < count * 6; j += TPB)
            out[(size_t)tile * 6 + j] = sout[j];
    }
}

extern "C" void kernel_launch(void* const* d_in, const int* in_sizes, int n_in,
                              void* d_out, int out_size)
{
    const uint4* in4 = (const uint4*)d_in[0];
    float* out = (float*)d_out;
    const int n_words = in_sizes[0] / 48;       // 1024*2048 = 2,097,152
    const int grid = (n_words + WPB - 1) / WPB; // 8192
    lzc48_kernel<<<grid, TPB>>>(in4, out, n_words);
}